// round 1
// baseline (speedup 1.0000x reference)
#include <cuda_runtime.h>

#define NB   32
#define LA   512
#define LB   512
#define DIM  768
#define OUTC (4*DIM)   // 3072

// Scratch (allocation-free rule: __device__ globals). 32 MB each.
__device__ float g_e [(size_t)NB * LA * LB];
__device__ float g_pb[(size_t)NB * LA * LB];

// ---------------------------------------------------------------------------
// Generic batched tiled GEMM: C[m,n] = sum_k A(m,k) * B(n,k)
//   A_KMAJ: A(m,k) = A[m*lda + k]   else A(m,k) = A[k*lda + m]
//   B_KMAJ: B(n,k) = B[n*ldb + k]   else B(n,k) = B[k*ldb + n]
// MODE 0: plain store to Out ([M,N] per batch)
// MODE 1: ESIM assembly epilogue: Out[(z*M+m)*OUTC + {0,1,2,3}*DIM + n] =
//         {Obase, acc, Obase-acc, Obase*acc}  where Obase is [M,DIM] per batch
// Tiles: 64x64x32, 256 threads, 4x4 per thread.
// ---------------------------------------------------------------------------
template<int MODE, bool A_KMAJ, bool B_KMAJ>
__global__ __launch_bounds__(256)
void gemm_k(const float* __restrict__ A, const float* __restrict__ Bp,
            const float* __restrict__ Obase, float* __restrict__ Out,
            int M, int N, int K, int lda, int ldb,
            long strideA, long strideB)
{
    __shared__ float As[64][33];   // [m][k], +1 pad for bank spread
    __shared__ float Bs[64][33];   // [n][k]

    const int tid = threadIdx.x;
    const int tx  = tid & 15;
    const int ty  = tid >> 4;
    const int z   = blockIdx.z;
    const int m0  = blockIdx.y * 64;
    const int n0  = blockIdx.x * 64;

    const float* Ab = A  + (size_t)z * strideA;
    const float* Bb = Bp + (size_t)z * strideB;

    float acc[4][4];
    #pragma unroll
    for (int i = 0; i < 4; i++)
        #pragma unroll
        for (int j = 0; j < 4; j++) acc[i][j] = 0.f;

    for (int kt = 0; kt < K; kt += 32) {
        __syncthreads();
        // ---- load A tile (64 m x 32 k) ----
        #pragma unroll
        for (int r = 0; r < 2; r++) {
            int lin = tid + r * 256;          // 0..511 float4 slots
            if (A_KMAJ) {
                int row = lin >> 3, k4 = lin & 7;
                float4 v = *(const float4*)(Ab + (size_t)(m0 + row) * lda + kt + k4 * 4);
                As[row][k4*4+0] = v.x; As[row][k4*4+1] = v.y;
                As[row][k4*4+2] = v.z; As[row][k4*4+3] = v.w;
            } else {
                int k = lin >> 4, m4 = lin & 15;
                float4 v = *(const float4*)(Ab + (size_t)(kt + k) * lda + m0 + m4 * 4);
                As[m4*4+0][k] = v.x; As[m4*4+1][k] = v.y;
                As[m4*4+2][k] = v.z; As[m4*4+3][k] = v.w;
            }
        }
        // ---- load B tile (64 n x 32 k) ----
        #pragma unroll
        for (int r = 0; r < 2; r++) {
            int lin = tid + r * 256;
            if (B_KMAJ) {
                int row = lin >> 3, k4 = lin & 7;
                float4 v = *(const float4*)(Bb + (size_t)(n0 + row) * ldb + kt + k4 * 4);
                Bs[row][k4*4+0] = v.x; Bs[row][k4*4+1] = v.y;
                Bs[row][k4*4+2] = v.z; Bs[row][k4*4+3] = v.w;
            } else {
                int k = lin >> 4, n4 = lin & 15;
                float4 v = *(const float4*)(Bb + (size_t)(kt + k) * ldb + n0 + n4 * 4);
                Bs[n4*4+0][k] = v.x; Bs[n4*4+1][k] = v.y;
                Bs[n4*4+2][k] = v.z; Bs[n4*4+3][k] = v.w;
            }
        }
        __syncthreads();

        #pragma unroll
        for (int kk = 0; kk < 32; kk++) {
            float a[4], b[4];
            #pragma unroll
            for (int i = 0; i < 4; i++) a[i] = As[ty*4+i][kk];
            #pragma unroll
            for (int j = 0; j < 4; j++) b[j] = Bs[tx*4+j][kk];
            #pragma unroll
            for (int i = 0; i < 4; i++)
                #pragma unroll
                for (int j = 0; j < 4; j++)
                    acc[i][j] = fmaf(a[i], b[j], acc[i][j]);
        }
    }

    if (MODE == 0) {
        float* C = Out + (size_t)z * M * N;
        #pragma unroll
        for (int i = 0; i < 4; i++) {
            int m = m0 + ty*4 + i;
            float4 v = make_float4(acc[i][0], acc[i][1], acc[i][2], acc[i][3]);
            *(float4*)(C + (size_t)m * N + n0 + tx * 4) = v;
        }
    } else {
        #pragma unroll
        for (int i = 0; i < 4; i++) {
            int m = m0 + ty*4 + i;
            const float4 av = *(const float4*)(Obase + ((size_t)z * M + m) * DIM + n0 + tx * 4);
            float4 t = make_float4(acc[i][0], acc[i][1], acc[i][2], acc[i][3]);
            float* orow = Out + ((size_t)z * M + m) * OUTC + n0 + tx * 4;
            *(float4*)(orow)            = av;
            *(float4*)(orow +     DIM)  = t;
            *(float4*)(orow + 2 * DIM)  = make_float4(av.x - t.x, av.y - t.y, av.z - t.z, av.w - t.w);
            *(float4*)(orow + 3 * DIM)  = make_float4(av.x * t.x, av.y * t.y, av.z * t.z, av.w * t.w);
        }
    }
}

// ---------------------------------------------------------------------------
// Row softmax (axis=2): normalize each row of e[b][a][:] in place. 512/row.
// ---------------------------------------------------------------------------
__global__ __launch_bounds__(256)
void row_softmax_k(float* __restrict__ e)
{
    __shared__ float red[256];
    float* p = e + (size_t)blockIdx.x * LB;
    int t = threadIdx.x;
    float v0 = p[t], v1 = p[t + 256];

    red[t] = fmaxf(v0, v1);
    __syncthreads();
    #pragma unroll
    for (int s = 128; s; s >>= 1) {
        if (t < s) red[t] = fmaxf(red[t], red[t + s]);
        __syncthreads();
    }
    float m = red[0];
    __syncthreads();

    float e0 = __expf(v0 - m), e1 = __expf(v1 - m);
    red[t] = e0 + e1;
    __syncthreads();
    #pragma unroll
    for (int s = 128; s; s >>= 1) {
        if (t < s) red[t] += red[t + s];
        __syncthreads();
    }
    float inv = 1.f / red[0];
    p[t]       = e0 * inv;
    p[t + 256] = e1 * inv;
}

// ---------------------------------------------------------------------------
// Column softmax (axis=1): for each (b,c), softmax over a. Reads raw e,
// writes P_b. One thread per column; coalesced across c.
// ---------------------------------------------------------------------------
__global__ __launch_bounds__(256)
void col_softmax_k(const float* __restrict__ e, float* __restrict__ pb)
{
    int z = blockIdx.y;
    int c = blockIdx.x * 256 + threadIdx.x;
    const float* base = e  + (size_t)z * LA * LB + c;
    float*       ob   = pb + (size_t)z * LA * LB + c;

    float m = -3.4e38f, s = 0.f;
    for (int a = 0; a < LA; a++) {
        float v = base[(size_t)a * LB];
        if (v > m) { s = s * __expf(m - v) + 1.f; m = v; }
        else       { s += __expf(v - m); }
    }
    float inv = 1.f / s;
    for (int a = 0; a < LA; a++) {
        float v = base[(size_t)a * LB];
        ob[(size_t)a * LB] = __expf(v - m) * inv;
    }
}

// ---------------------------------------------------------------------------
extern "C" void kernel_launch(void* const* d_in, const int* in_sizes, int n_in,
                              void* d_out, int out_size)
{
    const float* a_bar = (const float*)d_in[0];
    const float* b_bar = (const float*)d_in[1];
    float* out = (float*)d_out;
    float* m_a = out;
    float* m_b = out + (size_t)NB * LA * OUTC;

    float *pe = nullptr, *ppb = nullptr;
    cudaGetSymbolAddress((void**)&pe,  g_e);
    cudaGetSymbolAddress((void**)&ppb, g_pb);

    // K1: e[b] = a_bar[b] @ b_bar[b]^T   (both operands K-major)
    gemm_k<0, true, true><<<dim3(LB/64, LA/64, NB), 256>>>(
        a_bar, b_bar, nullptr, pe,
        LA, LB, DIM, DIM, DIM, (long)LA * DIM, (long)LB * DIM);

    // K2: column softmax (reads raw e) -> P_b
    col_softmax_k<<<dim3(LB/256, NB), 256>>>(pe, ppb);

    // K3: row softmax in place -> P_a
    row_softmax_k<<<NB * LA, 256>>>(pe);

    // K4: a_tilde = P_a @ b_bar, fused m_a assembly
    gemm_k<1, true, false><<<dim3(DIM/64, LA/64, NB), 256>>>(
        pe, b_bar, a_bar, m_a,
        LA, DIM, LB, LB, DIM, (long)LA * LB, (long)LB * DIM);

    // K5: b_tilde = P_b^T @ a_bar, fused m_b assembly
    gemm_k<1, false, false><<<dim3(DIM/64, LB/64, NB), 256>>>(
        ppb, a_bar, b_bar, m_b,
        LB, DIM, LA, LB, DIM, (long)LA * LB, (long)LA * DIM);
}

// round 3
// speedup vs baseline: 1.7049x; 1.7049x over previous
#include <cuda_runtime.h>
#include <cuda_bf16.h>
#include <cstdint>

#define NB   32
#define LA   512
#define LB   512
#define DIM  768
#define OUTC 3072

// ---------------- scratch (__device__ globals; no allocation allowed) -------
__device__ __align__(1024) __nv_bfloat16 g_ah [(size_t)NB*LA*DIM], g_al [(size_t)NB*LA*DIM];
__device__ __align__(1024) __nv_bfloat16 g_bh [(size_t)NB*LB*DIM], g_bl [(size_t)NB*LB*DIM];
__device__ __align__(1024) __nv_bfloat16 g_aTh[(size_t)NB*DIM*LA], g_aTl[(size_t)NB*DIM*LA];
__device__ __align__(1024) __nv_bfloat16 g_bTh[(size_t)NB*DIM*LB], g_bTl[(size_t)NB*DIM*LB];
__device__ __align__(1024) __nv_bfloat16 g_ph [(size_t)NB*LA*LB],  g_pl [(size_t)NB*LA*LB];
__device__ __align__(1024) __nv_bfloat16 g_pbTh[(size_t)NB*LB*LA], g_pbTl[(size_t)NB*LB*LA];
__device__ __align__(1024) float g_e[(size_t)NB*LA*LB];
__device__ float g_cmax[NB*LB], g_cinv[NB*LB];

// ---------------- low-level helpers (portable PTX only) ---------------------
__device__ __forceinline__ uint32_t smem_to_u32(const void* p) {
    uint32_t a;
    asm("{ .reg .u64 t; cvta.to.shared.u64 t, %1; cvt.u32.u64 %0, t; }" : "=r"(a) : "l"(p));
    return a;
}
__device__ __forceinline__ void cp16(uint32_t dst, const void* src) {
    asm volatile("cp.async.cg.shared.global [%0], [%1], 16;" :: "r"(dst), "l"(src));
}
__device__ __forceinline__ void cp_commit() { asm volatile("cp.async.commit_group;"); }
__device__ __forceinline__ void cp_wait1()  { asm volatile("cp.async.wait_group 1;"); }

__device__ __forceinline__ void ldsm4(uint32_t* r, uint32_t addr) {
    asm volatile("ldmatrix.sync.aligned.m8n8.x4.shared.b16 {%0,%1,%2,%3}, [%4];"
                 : "=r"(r[0]), "=r"(r[1]), "=r"(r[2]), "=r"(r[3]) : "r"(addr));
}
__device__ __forceinline__ void mma_bf16(float* c, const uint32_t* a, const uint32_t* b) {
    asm volatile("mma.sync.aligned.m16n8k16.row.col.f32.bf16.bf16.f32 "
                 "{%0,%1,%2,%3}, {%4,%5,%6,%7}, {%8,%9}, {%0,%1,%2,%3};"
                 : "+f"(c[0]), "+f"(c[1]), "+f"(c[2]), "+f"(c[3])
                 : "r"(a[0]), "r"(a[1]), "r"(a[2]), "r"(a[3]), "r"(b[0]), "r"(b[1]));
}

// ---------------- split-bf16 HMMA GEMM ---------------------------------------
// C[m,n] = sum_k (Ah+Al)(m,k)*(Bh+Bl)(n,k)  (drop Al*Bl). A,B K-major bf16.
// CTA tile 128x128, BK=32, 8 warps (2 M x 4 N), warp tile 64x32.
// smem tile layout per operand: [ks(2)][row(128)][16 bf16], 32B rows,
// chunk swizzle: 16B half kh stored at (kh ^ ((row>>2)&1)) -> ldmatrix
// phases hit 8 distinct banks.
#define TILE_BYTES 8192            // 2*128*32
#define STAGE_BYTES 32768          // 4 tiles
#define SMEM_DYN (2*STAGE_BYTES + 1024)

template<int MODE>   // 0: plain fp32 store; 1: ESIM epilogue into Out[M,3072]
__global__ __launch_bounds__(256)
void gemm_hmma(const __nv_bfloat16* __restrict__ Ah, const __nv_bfloat16* __restrict__ Al,
               const __nv_bfloat16* __restrict__ Bh, const __nv_bfloat16* __restrict__ Bl,
               const float* __restrict__ Obase, float* __restrict__ Out,
               int M, int N, int K)
{
    extern __shared__ char smraw[];
    uint32_t sm0 = smem_to_u32(smraw);
    uint32_t smb = (sm0 + 1023u) & ~1023u;

    const int tid = threadIdx.x;
    const int lid = tid & 31, wid = tid >> 5;
    const int wm = wid >> 2, wn = wid & 3;            // 2 x 4 warp grid
    const int z = blockIdx.z, m0 = blockIdx.y * 128, n0 = blockIdx.x * 128;

    const __nv_bfloat16* srcs[4] = {
        Ah + ((size_t)z * M + m0) * K, Al + ((size_t)z * M + m0) * K,
        Bh + ((size_t)z * N + n0) * K, Bl + ((size_t)z * N + n0) * K };

    // precompute ldmatrix lane offsets
    const int ar  = (lid & 7) | (((lid >> 3) & 1) << 3);   // 0..15 row-in-tile16
    const int akh = lid >> 4;
    uint32_t aoff[4];
    #pragma unroll
    for (int i = 0; i < 4; i++) {
        int m = wm * 64 + i * 16 + ar;
        aoff[i] = m * 32 + ((akh ^ ((m >> 2) & 1)) << 4);
    }
    const int br  = (lid & 7) | ((lid >> 4) << 3);
    const int bkh = (lid >> 3) & 1;
    uint32_t boff[2];
    #pragma unroll
    for (int j2 = 0; j2 < 2; j2++) {
        int n = wn * 32 + j2 * 16 + br;
        boff[j2] = n * 32 + ((bkh ^ ((n >> 2) & 1)) << 4);
    }

    float acc[4][4][4];
    #pragma unroll
    for (int i = 0; i < 4; i++)
        #pragma unroll
        for (int j = 0; j < 4; j++)
            #pragma unroll
            for (int r = 0; r < 4; r++) acc[i][j][r] = 0.f;

    const int nk = K >> 5;   // K / 32

    auto issue_stage = [&](int s, int kt) {
        uint32_t sb = smb + s * STAGE_BYTES;
        #pragma unroll
        for (int tl = 0; tl < 4; tl++) {
            const __nv_bfloat16* src = srcs[tl];
            uint32_t tb = sb + tl * TILE_BYTES;
            #pragma unroll
            for (int it = 0; it < 2; it++) {
                int idx = tid + it * 256;          // 0..511
                int m  = idx >> 2;
                int ks = (idx >> 1) & 1;
                int kh = idx & 1;
                uint32_t d = tb + ks * 4096 + m * 32 + ((kh ^ ((m >> 2) & 1)) << 4);
                cp16(d, src + (size_t)m * K + kt * 32 + ks * 16 + kh * 8);
            }
        }
    };

    issue_stage(0, 0);
    cp_commit();

    for (int kt = 0; kt < nk; kt++) {
        if (kt + 1 < nk) issue_stage((kt + 1) & 1, kt + 1);
        cp_commit();
        cp_wait1();
        __syncthreads();

        uint32_t st = smb + (kt & 1) * STAGE_BYTES;
        #pragma unroll
        for (int ks = 0; ks < 2; ks++) {
            uint32_t a_h[4][4], a_l[4][4], b_h[4][2], b_l[4][2];
            #pragma unroll
            for (int i = 0; i < 4; i++) {
                ldsm4(a_h[i], st + 0 * TILE_BYTES + ks * 4096 + aoff[i]);
                ldsm4(a_l[i], st + 1 * TILE_BYTES + ks * 4096 + aoff[i]);
            }
            #pragma unroll
            for (int j2 = 0; j2 < 2; j2++) {
                uint32_t rh[4], rl[4];
                ldsm4(rh, st + 2 * TILE_BYTES + ks * 4096 + boff[j2]);
                ldsm4(rl, st + 3 * TILE_BYTES + ks * 4096 + boff[j2]);
                b_h[j2*2+0][0] = rh[0]; b_h[j2*2+0][1] = rh[1];
                b_h[j2*2+1][0] = rh[2]; b_h[j2*2+1][1] = rh[3];
                b_l[j2*2+0][0] = rl[0]; b_l[j2*2+0][1] = rl[1];
                b_l[j2*2+1][0] = rl[2]; b_l[j2*2+1][1] = rl[3];
            }
            #pragma unroll
            for (int i = 0; i < 4; i++)
                #pragma unroll
                for (int j = 0; j < 4; j++) {
                    mma_bf16(acc[i][j], a_h[i], b_h[j]);
                    mma_bf16(acc[i][j], a_h[i], b_l[j]);
                    mma_bf16(acc[i][j], a_l[i], b_h[j]);
                }
        }
        __syncthreads();
    }

    // ---- epilogue: fragments -> global (32B sector stores) ----
    const int g = lid >> 2, t = lid & 3;
    #pragma unroll
    for (int i = 0; i < 4; i++) {
        #pragma unroll
        for (int j = 0; j < 4; j++) {
            int n = n0 + wn * 32 + j * 8 + t * 2;
            #pragma unroll
            for (int half = 0; half < 2; half++) {
                int m = m0 + wm * 64 + i * 16 + g + half * 8;
                float2 v = make_float2(acc[i][j][half*2+0], acc[i][j][half*2+1]);
                if (MODE == 0) {
                    *(float2*)(Out + ((size_t)z * M + m) * N + n) = v;
                } else {
                    float2 av = *(const float2*)(Obase + ((size_t)z * M + m) * DIM + n);
                    float* orow = Out + ((size_t)z * M + m) * OUTC + n;
                    *(float2*)(orow)           = av;
                    *(float2*)(orow + DIM)     = v;
                    *(float2*)(orow + 2*DIM)   = make_float2(av.x - v.x, av.y - v.y);
                    *(float2*)(orow + 3*DIM)   = make_float2(av.x * v.x, av.y * v.y);
                }
            }
        }
    }
}

// ---------------- bf16 split + transpose of fp32 input ----------------------
__global__ __launch_bounds__(256)
void conv_split_T(const float* __restrict__ X,
                  __nv_bfloat16* __restrict__ Xh,  __nv_bfloat16* __restrict__ Xl,
                  __nv_bfloat16* __restrict__ XTh, __nv_bfloat16* __restrict__ XTl,
                  int R, int C)
{
    __shared__ __nv_bfloat16 sh[64][65], sl[64][65];
    int z = blockIdx.z, r0 = blockIdx.y * 64, c0 = blockIdx.x * 64;
    #pragma unroll
    for (int it = 0; it < 16; it++) {
        int idx = threadIdx.x + it * 256;
        int i = idx >> 6, j = idx & 63;
        float v = X[((size_t)z * R + r0 + i) * C + c0 + j];
        __nv_bfloat16 h = __float2bfloat16(v);
        __nv_bfloat16 l = __float2bfloat16(v - __bfloat162float(h));
        Xh[((size_t)z * R + r0 + i) * C + c0 + j] = h;
        Xl[((size_t)z * R + r0 + i) * C + c0 + j] = l;
        sh[i][j] = h; sl[i][j] = l;
    }
    __syncthreads();
    #pragma unroll
    for (int it = 0; it < 16; it++) {
        int idx = threadIdx.x + it * 256;
        int j = idx >> 6, i = idx & 63;
        XTh[((size_t)z * C + c0 + j) * R + r0 + i] = sh[i][j];
        XTl[((size_t)z * C + c0 + j) * R + r0 + i] = sl[i][j];
    }
}

// ---------------- row softmax (axis=2) -> bf16 split P_a --------------------
__global__ __launch_bounds__(256)
void row_softmax_k(const float* __restrict__ e,
                   __nv_bfloat16* __restrict__ ph, __nv_bfloat16* __restrict__ pl)
{
    __shared__ float red[256];
    const float* p = e + (size_t)blockIdx.x * LB;
    int t = threadIdx.x;
    float v0 = p[t], v1 = p[t + 256];
    red[t] = fmaxf(v0, v1);
    __syncthreads();
    #pragma unroll
    for (int s = 128; s; s >>= 1) { if (t < s) red[t] = fmaxf(red[t], red[t + s]); __syncthreads(); }
    float m = red[0];
    __syncthreads();
    float e0 = __expf(v0 - m), e1 = __expf(v1 - m);
    red[t] = e0 + e1;
    __syncthreads();
    #pragma unroll
    for (int s = 128; s; s >>= 1) { if (t < s) red[t] += red[t + s]; __syncthreads(); }
    float inv = 1.f / red[0];
    float q0 = e0 * inv, q1 = e1 * inv;
    __nv_bfloat16 h0 = __float2bfloat16(q0), h1 = __float2bfloat16(q1);
    size_t base = (size_t)blockIdx.x * LB;
    ph[base + t] = h0;       pl[base + t]       = __float2bfloat16(q0 - __bfloat162float(h0));
    ph[base + t + 256] = h1; pl[base + t + 256] = __float2bfloat16(q1 - __bfloat162float(h1));
}

// ---------------- column stats (axis=1 softmax denom) ------------------------
__global__ __launch_bounds__(256)
void col_stats_k(const float* __restrict__ e, float* __restrict__ cmax, float* __restrict__ cinv)
{
    int z = blockIdx.y;
    int c = blockIdx.x * 256 + threadIdx.x;
    const float* base = e + (size_t)z * LA * LB + c;
    float m = -3.4e38f, s = 0.f;
    for (int a = 0; a < LA; a++) {
        float v = base[(size_t)a * LB];
        if (v > m) { s = s * __expf(m - v) + 1.f; m = v; }
        else       { s += __expf(v - m); }
    }
    cmax[z * LB + c] = m;
    cinv[z * LB + c] = 1.f / s;
}

// ---------------- column softmax + transpose -> bf16 split P_b^T ------------
__global__ __launch_bounds__(256)
void col_trans_k(const float* __restrict__ e, const float* __restrict__ cmax,
                 const float* __restrict__ cinv,
                 __nv_bfloat16* __restrict__ pbh, __nv_bfloat16* __restrict__ pbl)
{
    __shared__ float sp[64][65];
    int z = blockIdx.z, a0 = blockIdx.y * 64, c0 = blockIdx.x * 64;
    #pragma unroll
    for (int it = 0; it < 16; it++) {
        int idx = threadIdx.x + it * 256;
        int i = idx >> 6, j = idx & 63;      // i = a, j = c
        float v = e[((size_t)z * LA + a0 + i) * LB + c0 + j];
        sp[i][j] = __expf(v - cmax[z * LB + c0 + j]) * cinv[z * LB + c0 + j];
    }
    __syncthreads();
    #pragma unroll
    for (int it = 0; it < 16; it++) {
        int idx = threadIdx.x + it * 256;
        int j = idx >> 6, i = idx & 63;      // out row = c0+j, col = a0+i
        float q = sp[i][j];
        __nv_bfloat16 h = __float2bfloat16(q);
        pbh[((size_t)z * LB + c0 + j) * LA + a0 + i] = h;
        pbl[((size_t)z * LB + c0 + j) * LA + a0 + i] = __float2bfloat16(q - __bfloat162float(h));
    }
}

// ---------------------------------------------------------------------------
extern "C" void kernel_launch(void* const* d_in, const int* in_sizes, int n_in,
                              void* d_out, int out_size)
{
    const float* a_bar = (const float*)d_in[0];
    const float* b_bar = (const float*)d_in[1];
    float* out = (float*)d_out;
    float* m_a = out;
    float* m_b = out + (size_t)NB * LA * OUTC;

    __nv_bfloat16 *ah, *al, *bh, *bl, *aTh, *aTl, *bTh, *bTl, *ph, *pl, *pbh, *pbl;
    float *pe, *pcm, *pci;
    cudaGetSymbolAddress((void**)&ah,  g_ah);   cudaGetSymbolAddress((void**)&al,  g_al);
    cudaGetSymbolAddress((void**)&bh,  g_bh);   cudaGetSymbolAddress((void**)&bl,  g_bl);
    cudaGetSymbolAddress((void**)&aTh, g_aTh);  cudaGetSymbolAddress((void**)&aTl, g_aTl);
    cudaGetSymbolAddress((void**)&bTh, g_bTh);  cudaGetSymbolAddress((void**)&bTl, g_bTl);
    cudaGetSymbolAddress((void**)&ph,  g_ph);   cudaGetSymbolAddress((void**)&pl,  g_pl);
    cudaGetSymbolAddress((void**)&pbh, g_pbTh); cudaGetSymbolAddress((void**)&pbl, g_pbTl);
    cudaGetSymbolAddress((void**)&pe,  g_e);
    cudaGetSymbolAddress((void**)&pcm, g_cmax); cudaGetSymbolAddress((void**)&pci, g_cinv);

    cudaFuncSetAttribute(gemm_hmma<0>, cudaFuncAttributeMaxDynamicSharedMemorySize, SMEM_DYN);
    cudaFuncSetAttribute(gemm_hmma<1>, cudaFuncAttributeMaxDynamicSharedMemorySize, SMEM_DYN);

    // 1) bf16 split + transposed copies of inputs
    conv_split_T<<<dim3(DIM/64, LA/64, NB), 256>>>(a_bar, ah, al, aTh, aTl, LA, DIM);
    conv_split_T<<<dim3(DIM/64, LB/64, NB), 256>>>(b_bar, bh, bl, bTh, bTl, LB, DIM);

    // 2) e = a @ b^T   (M=LA, N=LB, K=DIM)
    gemm_hmma<0><<<dim3(LB/128, LA/128, NB), 256, SMEM_DYN>>>(
        ah, al, bh, bl, nullptr, pe, LA, LB, DIM);

    // 3) softmaxes -> split P_a [a,c] and P_b^T [c,a]
    row_softmax_k<<<NB * LA, 256>>>(pe, ph, pl);
    col_stats_k<<<dim3(LB/256, NB), 256>>>(pe, pcm, pci);
    col_trans_k<<<dim3(LB/64, LA/64, NB), 256>>>(pe, pcm, pci, pbh, pbl);

    // 4) a_tilde = P_a @ b  (M=LA, N=DIM, K=LB), fused m_a assembly
    gemm_hmma<1><<<dim3(DIM/128, LA/128, NB), 256, SMEM_DYN>>>(
        ph, pl, bTh, bTl, a_bar, m_a, LA, DIM, LB);

    // 5) b_tilde = P_b^T @ a (M=LB, N=DIM, K=LA), fused m_b assembly
    gemm_hmma<1><<<dim3(DIM/128, LB/128, NB), 256, SMEM_DYN>>>(
        pbh, pbl, aTh, aTl, b_bar, m_b, LB, DIM, LA);
}